// round 10
// baseline (speedup 1.0000x reference)
#include <cuda_runtime.h>
#include <math.h>
#include <stdint.h>

#define NN     8192
#define NB     8192
#define RANGEF 74000.0f
#define INV_W  ((float)NB / RANGEF)
#define GRID   148
#define TPB    1024
#define TBLK   16            // blocks that survive into the tail

// Scratch (__device__ globals; zero-initialized at load; every run restores
// them, so each graph replay sees identical initial state).
__device__ float4       g_A4[NN];     // 4 packed replicas per node (REDG target)
__device__ int          g_hist[NB];   // global histogram (REDG; zeroed in B2)
__device__ int          g_P[NB + 1];  // published exclusive prefix
__device__ int          g_ctr[NB];    // live scatter counters (re-inited in B2)
__device__ float        g_V[NN];      // bucket-grouped S values
__device__ float        g_C;          // dot(x, p)

// Barriers. g_arrive: all GRID blocks arrive, TBLK blocks poll.
// g_mb[k]: TBLK-block barriers. All reset by departure counting (replay-safe).
__device__ volatile int g_arrive;
__device__ int          g_adep;
__device__ volatile int g_mb[3];
__device__ int          g_mbdep[3];

// Monotone bucket map. MUST be identical at insert and query.
__device__ __forceinline__ int bucket_of(float v, float C) {
    float u = (v - C) * INV_W;
    int b = (int)u;
    if (b < 0) b = 0;
    if (b > NB - 1) b = NB - 1;
    return b;
}

// TBLK-block barrier: arrive, poll to full, then last-to-depart resets.
__device__ __forceinline__ void mbar(int k) {
    __syncthreads();
    if (threadIdx.x == 0) {
        __threadfence();                       // release this block's writes
        atomicAdd((int*)&g_mb[k], 1);
        while (g_mb[k] < TBLK) __nanosleep(32);
        __threadfence();                       // acquire others' writes
        if (atomicAdd(&g_mbdep[k], 1) == TBLK - 1) {
            g_mbdep[k] = 0;                    // everyone has passed: safe reset
            g_mb[k] = 0;
        }
    }
    __syncthreads();
}

// ---------------------------------------------------------------------------
__global__ void __launch_bounds__(TPB, 1)
fused(const int* __restrict__ ei, const float* __restrict__ p,
      const float* __restrict__ x, float* __restrict__ out,
      int E, int n, float logn) {

    __shared__ int sbuf[NB + 64];              // B4: staged P ; alias: dot wspace
    double* dsh = (double*)sbuf;

    const int t = threadIdx.x;
    const int b = blockIdx.x;

    // ---------------- Phase A: edges (blocks 0..GRID-2) + dot (last) -------
    if (b == GRID - 1) {
        double acc = 0.0;
        for (int i = t; i < n; i += TPB)
            acc += (double)x[i] * (double)p[i];
        dsh[t] = acc;
        __syncthreads();
        for (int s = TPB / 2; s > 0; s >>= 1) {
            if (t < s) dsh[t] += dsh[t + s];
            __syncthreads();
        }
        if (t == 0) g_C = (float)dsh[0];
    } else {
        const int nthr = (GRID - 1) * TPB;
        const int tid  = b * TPB + t;
        float* A = (float*)g_A4;               // node i replicas at A[4*i + rep]
        const int rep = t & 3;
        if ((E & 3) == 0 && (((unsigned long long)ei) & 15ull) == 0) {
            const int  E4 = E >> 2;
            const int4* s4 = (const int4*)ei;
            const int4* d4 = (const int4*)(ei + E);
            for (int j = tid; j < E4; j += nthr) {   // <=1 iter at this size
                int4 s = __ldg(&s4[j]);
                int4 d = __ldg(&d4[j]);
                float p0 = __ldg(&p[s.x]);
                float p1 = __ldg(&p[s.y]);
                float p2 = __ldg(&p[s.z]);
                float p3 = __ldg(&p[s.w]);
                atomicAdd(&A[4 * d.x + rep], p0);
                atomicAdd(&A[4 * d.y + rep], p1);
                atomicAdd(&A[4 * d.z + rep], p2);
                atomicAdd(&A[4 * d.w + rep], p3);
            }
        } else {
            for (int e = tid; e < E; e += nthr) {
                int s = __ldg(&ei[e]);
                int d = __ldg(&ei[E + e]);
                atomicAdd(&A[4 * d + rep], __ldg(&p[s]));
            }
        }
    }

    // ---------------- Global arrive barrier; blocks >= TBLK exit ------------
    __syncthreads();
    if (t == 0) {
        __threadfence();                       // publish REDGs / g_C
        atomicAdd((int*)&g_arrive, 1);
    }
    if (b >= TBLK) return;
    if (t == 0) {
        while (g_arrive < GRID) __nanosleep(32);
        __threadfence();                       // acquire
        if (atomicAdd(&g_adep, 1) == TBLK - 1) {
            g_adep = 0;                        // all pollers passed: reset
            g_arrive = 0;
        }
    }
    __syncthreads();

    // ================= Tail on TBLK blocks (512 nodes each) ================
    const float C = *(volatile float*)&g_C;

    // ---- B1: combine replicas + S + global histogram ----------------------
    float Si = 0.0f;
    int   myB = 0;
    const int myI = b * (NN / TBLK) + t;       // t < 512 active
    const bool mine = (t < NN / TBLK) && (myI < n);
    if (mine) {
        float4 a = __ldcg(&g_A4[myI]);
        g_A4[myI] = make_float4(0.f, 0.f, 0.f, 0.f);   // restore invariant
        float A  = (a.x + a.y) + (a.z + a.w);          // exact integer floats
        float pi = __ldg(&p[myI]);
        Si = pi * logn + logf(pi + A) + C;
        myB = bucket_of(Si, C);
        atomicAdd(&g_hist[myB], 1);            // REDG, ~1 op/bin
    }
    mbar(0);

    // ---- B2: block 0 scans 8192 bins (registers only) ---------------------
    if (b == 0) {
        int base8 = t * 8;
        int c8[8];
#pragma unroll
        for (int k = 0; k < 8; k++) {
            c8[k] = __ldcg(&g_hist[base8 + k]);
            g_hist[base8 + k] = 0;             // restore invariant
        }
        int ex[8], tot = 0;
#pragma unroll
        for (int k = 0; k < 8; k++) { ex[k] = tot; tot += c8[k]; }

        __shared__ int wsum[32];
        int lane = t & 31, wid = t >> 5;
        int v = tot;
#pragma unroll
        for (int o = 1; o < 32; o <<= 1) {
            int u = __shfl_up_sync(0xffffffffu, v, o);
            if (lane >= o) v += u;
        }
        if (lane == 31) wsum[wid] = v;
        __syncthreads();
        if (wid == 0) {
            int w = wsum[lane];
#pragma unroll
            for (int o = 1; o < 32; o <<= 1) {
                int u = __shfl_up_sync(0xffffffffu, w, o);
                if (lane >= o) w += u;
            }
            wsum[lane] = w;
        }
        __syncthreads();
        int excl = v - tot + (wid ? wsum[wid - 1] : 0);

#pragma unroll
        for (int k = 0; k < 8; k++) {
            int pref = excl + ex[k];
            g_P[base8 + k]   = pref;
            g_ctr[base8 + k] = pref;           // live counters for scatter
        }
        if (t == TPB - 1) g_P[NB] = excl + tot;
    }
    mbar(1);

    // ---- B3: scatter own nodes into g_V ------------------------------------
    if (mine) {
        int pos = atomicAdd(&g_ctr[myB], 1);   // ATOM w/ return, ~1 conflict
        g_V[pos] = Si;
    }
    mbar(2);

    // ---- B4: output. Stage P in smem; band from g_V ------------------------
    // out[i] = sum_j tanh(1000*(S_i - S_j) - 5). Outside band
    // [Si-0.015, Si+0.005]: exactly saturated (+1/-1) -> prefix counts.
    // Band buckets: exact per-element evaluation (incl. diagonal j=i).
#pragma unroll
    for (int k = 0; k < 8; k++)
        sbuf[t + TPB * k] = __ldcg(&g_P[t + TPB * k]);
    if (t == 0) sbuf[NB] = __ldcg(&g_P[NB]);
    __syncthreads();

    if (mine) {
        const float K   = 1000.0f;
        const float EPS = 5.0f;
        const float CUT = 10.0f;

        int loB = bucket_of(Si - 0.015f, C);
        int hiB = bucket_of(Si + 0.005f, C);

        int pLo = sbuf[loB];
        int pHi = sbuf[hiB + 1];
        float acc = (float)pLo - (float)(n - pHi);

        for (int idx = pLo; idx < pHi; ++idx) {
            float w   = __ldcg(&g_V[idx]);
            float arg = K * (Si - w) - EPS;
            if (arg > CUT)        acc += 1.0f;
            else if (arg < -CUT)  acc -= 1.0f;
            else                  acc += tanhf(arg);
        }
        out[myI] = acc;                        // coalesced
    }
}

// ---------------------------------------------------------------------------
extern "C" void kernel_launch(void* const* d_in, const int* in_sizes, int n_in,
                              void* d_out, int out_size) {
    const int*   ei = (const int*)d_in[0];     // (2, E) row-major
    const float* p  = (const float*)d_in[1];   // (N,)
    const float* x  = (const float*)d_in[2];   // (N, 1)

    int E = in_sizes[0] / 2;
    int n = in_sizes[1];
    float logn = logf((float)n);

    fused<<<GRID, TPB>>>(ei, p, x, (float*)d_out, E, n, logn);
}

// round 11
// speedup vs baseline: 1.2821x; 1.2821x over previous
#include <cuda_runtime.h>
#include <math.h>
#include <stdint.h>

#define NN     8192
#define NB     8192
#define RANGEF 74000.0f
#define INV_W  ((float)NB / RANGEF)
#define GRID   148
#define TPB    1024

// Scratch (__device__ globals; zero-initialized at load; g_A reset by block 0
// and g_arrive reset to 0 every run -> every graph replay sees clean state).
__device__ float        g_A[NN];    // edge segment sums (single copy)
__device__ float        g_C;        // dot(x, p)
__device__ volatile int g_arrive;   // arrive-only barrier counter

// Monotone bucket map. MUST be identical at insert and query.
__device__ __forceinline__ int bucket_of(float v, float C) {
    float u = (v - C) * INV_W;
    int b = (int)u;
    if (b < 0) b = 0;
    if (b > NB - 1) b = NB - 1;
    return b;
}

// ---------------------------------------------------------------------------
__global__ void __launch_bounds__(TPB, 1)
fused(const int* __restrict__ ei, const float* __restrict__ p,
      const float* __restrict__ x, float* __restrict__ out,
      int E, int n, float logn) {

    // Dynamic smem: sp[NN] (staged p) | cnt[NB] | sV[NN] | wsum[32]
    extern __shared__ int dsm[];
    float*  sp   = (float*)dsm;
    int*    cnt  = dsm + NN;
    float*  sV   = (float*)(dsm + NN + NB);
    int*    wsum = dsm + NN + 2 * NB;
    double* dsh  = (double*)dsm;            // alias: dot workspace (last block)

    const int t = threadIdx.x;
    const int b = blockIdx.x;

    // ---------------- Phase A: edges (blocks 0..GRID-2) + dot (last) -------
    if (b == GRID - 1) {
        double acc = 0.0;
        for (int i = t; i < n; i += TPB)
            acc += (double)x[i] * (double)p[i];
        dsh[t] = acc;
        __syncthreads();
        for (int s = TPB / 2; s > 0; s >>= 1) {
            if (t < s) dsh[t] += dsh[t + s];
            __syncthreads();
        }
        if (t == 0) g_C = (float)dsh[0];
    } else {
        // Stage p into smem (coalesced float4), then gather via LDS:
        // random LDS ~ conflict-degree cost (~4 cyc) vs ~32 L1tex wavefronts.
        {
            const float4* p4 = (const float4*)p;
            float4*       s4 = (float4*)sp;
#pragma unroll
            for (int k = 0; k < NN / (TPB * 4); k++)
                s4[t + TPB * k] = __ldg(&p4[t + TPB * k]);
        }
        __syncthreads();

        const int nthr = (GRID - 1) * TPB;
        const int tid  = b * TPB + t;
        if ((E & 3) == 0 && (((unsigned long long)ei) & 15ull) == 0) {
            const int  E4 = E >> 2;
            const int4* s4 = (const int4*)ei;
            const int4* d4 = (const int4*)(ei + E);
            for (int j = tid; j < E4; j += nthr) {    // <=1 iter at this size
                int4 s = __ldg(&s4[j]);
                int4 d = __ldg(&d4[j]);
                float p0 = sp[s.x];                   // LDS gathers
                float p1 = sp[s.y];
                float p2 = sp[s.z];
                float p3 = sp[s.w];
                atomicAdd(&g_A[d.x], p0);             // REDG, fire-and-forget
                atomicAdd(&g_A[d.y], p1);
                atomicAdd(&g_A[d.z], p2);
                atomicAdd(&g_A[d.w], p3);
            }
        } else {
            for (int e = tid; e < E; e += nthr) {
                int s = __ldg(&ei[e]);
                int d = __ldg(&ei[E + e]);
                atomicAdd(&g_A[d], sp[s]);
            }
        }
    }

    // ---------------- Arrive-only barrier ----------------------------------
    __threadfence();                        // drain REDGs / publish g_C
    __syncthreads();
    if (b != 0) {
        if (t == 0) atomicAdd((int*)&g_arrive, 1);
        return;                             // blocks 1..GRID-1 are DONE
    }
    if (t == 0) {
        while (g_arrive != GRID - 1) __nanosleep(32);
        g_arrive = 0;                       // reset for next graph replay
        __threadfence();
    }
    __syncthreads();

    // ================= Block 0 serial tail (all in smem/regs) ==============
    // Zero histogram.
#pragma unroll
    for (int k = 0; k < NB / TPB; k++) cnt[t + TPB * k] = 0;
    __syncthreads();

    const float C = *(volatile float*)&g_C;

    // Combine + S + histogram. Node map i = t + 1024k reused for output.
    float sv[NN / TPB];
    int   bk[NN / TPB];
#pragma unroll
    for (int k = 0; k < NN / TPB; k++) {
        int i = t + TPB * k;
        float A = __ldcg(&g_A[i]);          // L2 (REDG-written)
        g_A[i] = 0.0f;                      // restore invariant for replay
        float pi = sp[i];                   // already staged (conflict-free LDS)
        float s  = pi * logn + logf(pi + A) + C;
        sv[k] = s;
        int bb = bucket_of(s, C);
        bk[k] = bb;
        atomicAdd(&cnt[bb], 1);             // smem, spread addresses
    }
    __syncthreads();

    // Exclusive scan over 8192 bins: 8 serial per thread + shuffle scan.
    int base8 = t * 8;
    int ex[8];
    int tot = 0;
#pragma unroll
    for (int k = 0; k < 8; k++) { ex[k] = tot; tot += cnt[base8 + k]; }

    int lane = t & 31, wid = t >> 5;
    int v = tot;
#pragma unroll
    for (int o = 1; o < 32; o <<= 1) {
        int u = __shfl_up_sync(0xffffffffu, v, o);
        if (lane >= o) v += u;
    }
    if (lane == 31) wsum[wid] = v;
    __syncthreads();
    if (wid == 0) {
        int w = wsum[lane];
#pragma unroll
        for (int o = 1; o < 32; o <<= 1) {
            int u = __shfl_up_sync(0xffffffffu, w, o);
            if (lane >= o) w += u;
        }
        wsum[lane] = w;
    }
    __syncthreads();
    int excl = v - tot + (wid ? wsum[wid - 1] : 0);

#pragma unroll
    for (int k = 0; k < 8; k++)
        cnt[base8 + k] = excl + ex[k];      // live counters (= bucket starts)
    __syncthreads();

    // Counting-sort scatter into smem. Afterwards cnt[b] == P[b+1] (ends).
#pragma unroll
    for (int k = 0; k < NN / TPB; k++) {
        int pos = atomicAdd(&cnt[bk[k]], 1);
        sV[pos] = sv[k];
    }
    __syncthreads();

    // Output: out[i] = sum_j tanh(1000*(S_i - S_j) - 5). Outside band
    // [Si-0.015, Si+0.005]: exactly saturated (+1/-1) -> prefix counts
    // (pLo = P[loB] = cnt[loB-1], pHi = P[hiB+1] = cnt[hiB]).
    // Band buckets: exact per-element evaluation (incl. diagonal j=i).
    const float K   = 1000.0f;
    const float EPS = 5.0f;
    const float CUT = 10.0f;
#pragma unroll
    for (int k = 0; k < NN / TPB; k++) {
        int i = t + TPB * k;
        if (i >= n) break;
        float Si = sv[k];

        int loB = bucket_of(Si - 0.015f, C);
        int hiB = bucket_of(Si + 0.005f, C);

        int pLo = (loB > 0) ? cnt[loB - 1] : 0;
        int pHi = cnt[hiB];
        float acc = (float)pLo - (float)(n - pHi);

        for (int idx = pLo; idx < pHi; ++idx) {
            float w   = sV[idx];
            float arg = K * (Si - w) - EPS;
            if (arg > CUT)        acc += 1.0f;
            else if (arg < -CUT)  acc -= 1.0f;
            else                  acc += tanhf(arg);
        }
        out[i] = acc;                       // coalesced
    }
}

// ---------------------------------------------------------------------------
extern "C" void kernel_launch(void* const* d_in, const int* in_sizes, int n_in,
                              void* d_out, int out_size) {
    const int*   ei = (const int*)d_in[0];     // (2, E) row-major
    const float* p  = (const float*)d_in[1];   // (N,)
    const float* x  = (const float*)d_in[2];   // (N, 1)

    int E = in_sizes[0] / 2;
    int n = in_sizes[1];
    float logn = logf((float)n);

    const int smem = (NN + 2 * NB + 32) * (int)sizeof(int);   // 98,432 bytes
    cudaFuncSetAttribute(fused, cudaFuncAttributeMaxDynamicSharedMemorySize, smem);
    fused<<<GRID, TPB, smem>>>(ei, p, x, (float*)d_out, E, n, logn);
}

// round 12
// speedup vs baseline: 1.3661x; 1.0655x over previous
#include <cuda_runtime.h>
#include <math.h>
#include <stdint.h>

#define NN     8192
#define NB     8192
#define RANGEF 74000.0f
#define INV_W  ((float)NB / RANGEF)
#define WB     64              // worker blocks (edge phase)
#define GRID   (WB + 1)        // + block 0 (tail)
#define TPB    1024

// Scratch (__device__ globals; zero-initialized at load; g_A and g_arrive are
// restored every run -> each graph replay sees identical initial state).
__device__ float        g_A[NN];    // edge segment sums
__device__ volatile int g_arrive;   // arrive-only barrier counter

// Monotone bucket map. MUST be identical at insert and query.
__device__ __forceinline__ int bucket_of(float v, float C) {
    float u = (v - C) * INV_W;
    int b = (int)u;
    if (b < 0) b = 0;
    if (b > NB - 1) b = NB - 1;
    return b;
}

// ---------------------------------------------------------------------------
__global__ void __launch_bounds__(TPB, 1)
fused(const int* __restrict__ ei, const float* __restrict__ p,
      const float* __restrict__ x, float* __restrict__ out,
      int E, int n, float logn) {

    // Dynamic smem: sp[NN] (staged p) | cnt[NB] | sV[NN]
    extern __shared__ int dsm[];
    float* sp  = (float*)dsm;
    int*   cnt = dsm + NN;
    float* sV  = (float*)(dsm + NN + NB);
    __shared__ int    wsum[32];
    __shared__ double dred[32];

    const int t = threadIdx.x;
    const int b = blockIdx.x;
    const int lane = t & 31, wid = t >> 5;

    if (b != 0) {
        // ================= Worker blocks 1..WB: edge scatter ================
        // Stage p into smem (coalesced float4) -> random gathers become LDS.
        {
            const float4* p4 = (const float4*)p;
            float4*       s4 = (float4*)sp;
#pragma unroll
            for (int k = 0; k < NN / (TPB * 4); k++)
                s4[t + TPB * k] = __ldg(&p4[t + TPB * k]);
        }
        __syncthreads();

        const int tid = (b - 1) * TPB + t;
        if ((E & 3) == 0 && (((unsigned long long)ei) & 15ull) == 0) {
            const int  E4 = E >> 2;
            const int4* s4 = (const int4*)ei;
            const int4* d4 = (const int4*)(ei + E);
            for (int j = tid; j < E4; j += WB * TPB) {   // exactly 1 iter here
                int4 s = __ldg(&s4[j]);
                int4 d = __ldg(&d4[j]);
                float p0 = sp[s.x];
                float p1 = sp[s.y];
                float p2 = sp[s.z];
                float p3 = sp[s.w];
                atomicAdd(&g_A[d.x], p0);                // REDG fire-and-forget
                atomicAdd(&g_A[d.y], p1);
                atomicAdd(&g_A[d.z], p2);
                atomicAdd(&g_A[d.w], p3);
            }
        } else {
            for (int e = tid; e < E; e += WB * TPB) {
                int s = __ldg(&ei[e]);
                int d = __ldg(&ei[E + e]);
                atomicAdd(&g_A[d], sp[s]);
            }
        }

        __threadfence();                    // drain REDGs to global visibility
        __syncthreads();
        if (t == 0) atomicAdd((int*)&g_arrive, 1);
        return;                             // workers are DONE
    }

    // ================= Block 0: pre-barrier overlap work ====================
    // Stage p, zero histogram, compute C = dot(x,p) -- all while workers run.
    {
        const float4* p4 = (const float4*)p;
        float4*       s4 = (float4*)sp;
#pragma unroll
        for (int k = 0; k < NN / (TPB * 4); k++)
            s4[t + TPB * k] = __ldg(&p4[t + TPB * k]);
    }
#pragma unroll
    for (int k = 0; k < NB / TPB; k++) cnt[t + TPB * k] = 0;

    // Deterministic double dot: 8 strided elems/thread, warp shuffle, tree.
    double acc = 0.0;
    for (int i = t; i < n; i += TPB)
        acc += (double)__ldg(&x[i]) * (double)__ldg(&p[i]);
#pragma unroll
    for (int o = 16; o > 0; o >>= 1)
        acc += __shfl_down_sync(0xffffffffu, acc, o);
    if (lane == 0) dred[wid] = acc;
    __syncthreads();
    if (wid == 0) {
        double a2 = dred[lane];
#pragma unroll
        for (int o = 16; o > 0; o >>= 1)
            a2 += __shfl_down_sync(0xffffffffu, a2, o);
        if (lane == 0) dred[0] = a2;
    }
    __syncthreads();
    const float C = (float)dred[0];

    // ---------------- Wait for all workers ---------------------------------
    if (t == 0) {
        while (g_arrive != WB) __nanosleep(32);
        g_arrive = 0;                       // reset for next graph replay
        __threadfence();                    // acquire workers' REDGs
    }
    __syncthreads();

    // ================= Tail (all in smem/regs) ==============================
    // Combine + S + histogram. Node map i = t + 1024k reused for output.
    float sv[NN / TPB];
    int   bk[NN / TPB];
    {
        float4* A4 = (float4*)g_A;
        const float4 z4 = make_float4(0.f, 0.f, 0.f, 0.f);
#pragma unroll
        for (int k = 0; k < NN / (TPB * 4); k++) {
            int i4 = t + TPB * k;
            float4 a = __ldcg(&A4[i4]);     // L2 (REDG-written)
            A4[i4] = z4;                    // restore invariant for replay
            float av[4] = {a.x, a.y, a.z, a.w};
#pragma unroll
            for (int q = 0; q < 4; q++) {
                int i = 4 * i4 + q;         // i = 4*(t + 1024k) + q
                float pi = sp[i];
                float s  = pi * logn + logf(pi + av[q]) + C;
                sv[4 * k + q] = s;
                int bb = bucket_of(s, C);
                bk[4 * k + q] = bb;
                atomicAdd(&cnt[bb], 1);     // smem, spread addresses
            }
        }
    }
    __syncthreads();

    // Exclusive scan over 8192 bins: 8 serial per thread + shuffle scan.
    int base8 = t * 8;
    int ex[8];
    int tot = 0;
#pragma unroll
    for (int k = 0; k < 8; k++) { ex[k] = tot; tot += cnt[base8 + k]; }

    int v = tot;
#pragma unroll
    for (int o = 1; o < 32; o <<= 1) {
        int u = __shfl_up_sync(0xffffffffu, v, o);
        if (lane >= o) v += u;
    }
    if (lane == 31) wsum[wid] = v;
    __syncthreads();
    if (wid == 0) {
        int w = wsum[lane];
#pragma unroll
        for (int o = 1; o < 32; o <<= 1) {
            int u = __shfl_up_sync(0xffffffffu, w, o);
            if (lane >= o) w += u;
        }
        wsum[lane] = w;
    }
    __syncthreads();
    int excl = v - tot + (wid ? wsum[wid - 1] : 0);

#pragma unroll
    for (int k = 0; k < 8; k++)
        cnt[base8 + k] = excl + ex[k];      // live counters (= bucket starts)
    __syncthreads();

    // Counting-sort scatter into smem. Afterwards cnt[b] == P[b+1] (ends).
#pragma unroll
    for (int k = 0; k < NN / TPB; k++) {
        int pos = atomicAdd(&cnt[bk[k]], 1);
        sV[pos] = sv[k];
    }
    __syncthreads();

    // Output: out[i] = sum_j tanh(1000*(S_i - S_j) - 5). Outside band
    // [Si-0.015, Si+0.005]: exactly saturated (+1/-1) -> prefix counts
    // (pLo = P[loB] = cnt[loB-1], pHi = P[hiB+1] = cnt[hiB]).
    // Band buckets: exact per-element evaluation (incl. diagonal j=i).
    const float K   = 1000.0f;
    const float EPS = 5.0f;
    const float CUT = 10.0f;
#pragma unroll
    for (int k = 0; k < NN / TPB; k++) {
        // NOTE: i mapping here is 4*(t + 1024*(k/4)) + (k%4); recompute:
        int i = 4 * (t + TPB * (k >> 2)) + (k & 3);
        if (i >= n) continue;
        float Si = sv[k];

        int loB = bucket_of(Si - 0.015f, C);
        int hiB = bucket_of(Si + 0.005f, C);

        int pLo = (loB > 0) ? cnt[loB - 1] : 0;
        int pHi = cnt[hiB];
        float facc = (float)pLo - (float)(n - pHi);

        for (int idx = pLo; idx < pHi; ++idx) {
            float w   = sV[idx];
            float arg = K * (Si - w) - EPS;
            if (arg > CUT)        facc += 1.0f;
            else if (arg < -CUT)  facc -= 1.0f;
            else                  facc += tanhf(arg);
        }
        out[i] = facc;                      // 16B-coalesced per thread
    }
}

// ---------------------------------------------------------------------------
extern "C" void kernel_launch(void* const* d_in, const int* in_sizes, int n_in,
                              void* d_out, int out_size) {
    const int*   ei = (const int*)d_in[0];     // (2, E) row-major
    const float* p  = (const float*)d_in[1];   // (N,)
    const float* x  = (const float*)d_in[2];   // (N, 1)

    int E = in_sizes[0] / 2;
    int n = in_sizes[1];
    float logn = logf((float)n);

    const int smem = (NN + 2 * NB) * (int)sizeof(int);   // 98,304 bytes
    cudaFuncSetAttribute(fused, cudaFuncAttributeMaxDynamicSharedMemorySize, smem);
    fused<<<GRID, TPB, smem>>>(ei, p, x, (float*)d_out, E, n, logn);
}

// round 13
// speedup vs baseline: 1.4898x; 1.0906x over previous
#include <cuda_runtime.h>
#include <math.h>
#include <stdint.h>

#define NN     8192
#define NB     8192
#define RANGEF 74000.0f
#define INV_W  ((float)NB / RANGEF)
#define WB     64              // worker blocks (edge phase)
#define GRID   (WB + 1)        // + block 0 (tail)
#define TPB    1024

// Scratch (__device__ globals; zero-initialized at load; g_A and g_arrive are
// restored every run -> each graph replay sees identical initial state).
__device__ float        g_A[NN];    // edge segment sums
__device__ volatile int g_arrive;   // arrive-only barrier counter

// Monotone bucket map. MUST be identical at insert and query.
__device__ __forceinline__ int bucket_of(float v, float C) {
    float u = (v - C) * INV_W;
    int b = (int)u;
    if (b < 0) b = 0;
    if (b > NB - 1) b = NB - 1;
    return b;
}

// HW tanh (MUFU.TANH, sm_75+). Abs err ~2^-10.6 — band terms only, negligible.
__device__ __forceinline__ float tanh_fast(float a) {
    float r;
    asm("tanh.approx.f32 %0, %1;" : "=f"(r) : "f"(a));
    return r;
}

// ---------------------------------------------------------------------------
__global__ void __launch_bounds__(TPB, 1)
fused(const int* __restrict__ ei, const float* __restrict__ p,
      const float* __restrict__ x, float* __restrict__ out,
      int E, int n, float logn) {

    // Dynamic smem: sp[NN] (staged p) | cnt[NB] | sV[NN]
    extern __shared__ int dsm[];
    float* sp  = (float*)dsm;
    int*   cnt = dsm + NN;
    float* sV  = (float*)(dsm + NN + NB);
    __shared__ int    wsum[32];
    __shared__ double dred[32];

    const int t = threadIdx.x;
    const int b = blockIdx.x;
    const int lane = t & 31, wid = t >> 5;

    if (b != 0) {
        // ================= Worker blocks 1..WB: edge scatter ================
        {
            const float4* p4 = (const float4*)p;
            float4*       s4 = (float4*)sp;
#pragma unroll
            for (int k = 0; k < NN / (TPB * 4); k++)
                s4[t + TPB * k] = __ldg(&p4[t + TPB * k]);
        }
        __syncthreads();

        const int tid = (b - 1) * TPB + t;
        if ((E & 3) == 0 && (((unsigned long long)ei) & 15ull) == 0) {
            const int  E4 = E >> 2;
            const int4* s4 = (const int4*)ei;
            const int4* d4 = (const int4*)(ei + E);
            for (int j = tid; j < E4; j += WB * TPB) {   // exactly 1 iter here
                int4 s = __ldg(&s4[j]);
                int4 d = __ldg(&d4[j]);
                float p0 = sp[s.x];
                float p1 = sp[s.y];
                float p2 = sp[s.z];
                float p3 = sp[s.w];
                atomicAdd(&g_A[d.x], p0);                // REDG fire-and-forget
                atomicAdd(&g_A[d.y], p1);
                atomicAdd(&g_A[d.z], p2);
                atomicAdd(&g_A[d.w], p3);
            }
        } else {
            for (int e = tid; e < E; e += WB * TPB) {
                int s = __ldg(&ei[e]);
                int d = __ldg(&ei[E + e]);
                atomicAdd(&g_A[d], sp[s]);
            }
        }

        __threadfence();                    // drain REDGs to global visibility
        __syncthreads();
        if (t == 0) atomicAdd((int*)&g_arrive, 1);
        return;                             // workers are DONE
    }

    // ================= Block 0: pre-barrier overlap work ====================
    {
        const float4* p4 = (const float4*)p;
        float4*       s4 = (float4*)sp;
#pragma unroll
        for (int k = 0; k < NN / (TPB * 4); k++)
            s4[t + TPB * k] = __ldg(&p4[t + TPB * k]);
    }
#pragma unroll
    for (int k = 0; k < NB / TPB; k++) cnt[t + TPB * k] = 0;

    // Deterministic double dot: warp shuffle + tree (overlaps with workers).
    double acc = 0.0;
    for (int i = t; i < n; i += TPB)
        acc += (double)__ldg(&x[i]) * (double)__ldg(&p[i]);
#pragma unroll
    for (int o = 16; o > 0; o >>= 1)
        acc += __shfl_down_sync(0xffffffffu, acc, o);
    if (lane == 0) dred[wid] = acc;
    __syncthreads();
    if (wid == 0) {
        double a2 = dred[lane];
#pragma unroll
        for (int o = 16; o > 0; o >>= 1)
            a2 += __shfl_down_sync(0xffffffffu, a2, o);
        if (lane == 0) dred[0] = a2;
    }
    __syncthreads();
    const float C = (float)dred[0];

    // ---------------- Wait for all workers ---------------------------------
    if (t == 0) {
        while (g_arrive != WB) __nanosleep(32);
        g_arrive = 0;                       // reset for next graph replay
        __threadfence();                    // acquire workers' REDGs
    }
    __syncthreads();

    // ================= Tail (all in smem/regs) ==============================
    // Combine + S + histogram. __logf: sub-ulp of S (~4e5, ulp 0.03).
    float sv[NN / TPB];
    int   bk[NN / TPB];
    {
        float4* A4 = (float4*)g_A;
        const float4 z4 = make_float4(0.f, 0.f, 0.f, 0.f);
#pragma unroll
        for (int k = 0; k < NN / (TPB * 4); k++) {
            int i4 = t + TPB * k;
            float4 a = __ldcg(&A4[i4]);     // L2 (REDG-written)
            A4[i4] = z4;                    // restore invariant for replay
            float av[4] = {a.x, a.y, a.z, a.w};
#pragma unroll
            for (int q = 0; q < 4; q++) {
                int i = 4 * i4 + q;         // i = 4*(t + 1024k) + q
                float pi = sp[i];
                float s  = pi * logn + __logf(pi + av[q]) + C;
                sv[4 * k + q] = s;
                int bb = bucket_of(s, C);
                bk[4 * k + q] = bb;
                atomicAdd(&cnt[bb], 1);     // smem, spread addresses
            }
        }
    }
    __syncthreads();

    // Exclusive scan over 8192 bins: 8 serial per thread + shuffle scan.
    int base8 = t * 8;
    int ex[8];
    int tot = 0;
#pragma unroll
    for (int k = 0; k < 8; k++) { ex[k] = tot; tot += cnt[base8 + k]; }

    int v = tot;
#pragma unroll
    for (int o = 1; o < 32; o <<= 1) {
        int u = __shfl_up_sync(0xffffffffu, v, o);
        if (lane >= o) v += u;
    }
    if (lane == 31) wsum[wid] = v;
    __syncthreads();
    if (wid == 0) {
        int w = wsum[lane];
#pragma unroll
        for (int o = 1; o < 32; o <<= 1) {
            int u = __shfl_up_sync(0xffffffffu, w, o);
            if (lane >= o) w += u;
        }
        wsum[lane] = w;
    }
    __syncthreads();
    int excl = v - tot + (wid ? wsum[wid - 1] : 0);

#pragma unroll
    for (int k = 0; k < 8; k++)
        cnt[base8 + k] = excl + ex[k];      // live counters (= bucket starts)
    __syncthreads();

    // Counting-sort scatter into smem. Afterwards cnt[b] == P[b+1] (ends).
#pragma unroll
    for (int k = 0; k < NN / TPB; k++) {
        int pos = atomicAdd(&cnt[bk[k]], 1);
        sV[pos] = sv[k];
    }
    __syncthreads();

    // Output: out[i] = sum_j tanh(1000*(S_i - S_j) - 5). Outside band
    // [Si-0.015, Si+0.005]: exactly saturated (+1/-1) -> prefix counts
    // (pLo = P[loB] = cnt[loB-1], pHi = P[hiB+1] = cnt[hiB]).
    // Band buckets: exact per-element evaluation (incl. diagonal j=i).
    const float K   = 1000.0f;
    const float EPS = 5.0f;
    const float CUT = 10.0f;
#pragma unroll
    for (int k = 0; k < NN / TPB; k++) {
        int i = 4 * (t + TPB * (k >> 2)) + (k & 3);
        if (i >= n) continue;
        float Si = sv[k];

        int loB = bucket_of(Si - 0.015f, C);
        int hiB = bucket_of(Si + 0.005f, C);

        int pLo = (loB > 0) ? cnt[loB - 1] : 0;
        int pHi = cnt[hiB];
        float facc = (float)pLo - (float)(n - pHi);

        for (int idx = pLo; idx < pHi; ++idx) {
            float w   = sV[idx];
            float arg = K * (Si - w) - EPS;
            if (arg > CUT)        facc += 1.0f;
            else if (arg < -CUT)  facc -= 1.0f;
            else                  facc += tanh_fast(arg);
        }
        out[i] = facc;                      // 16B-coalesced per thread
    }
}

// ---------------------------------------------------------------------------
extern "C" void kernel_launch(void* const* d_in, const int* in_sizes, int n_in,
                              void* d_out, int out_size) {
    const int*   ei = (const int*)d_in[0];     // (2, E) row-major
    const float* p  = (const float*)d_in[1];   // (N,)
    const float* x  = (const float*)d_in[2];   // (N, 1)

    int E = in_sizes[0] / 2;
    int n = in_sizes[1];
    float logn = logf((float)n);

    const int smem = (NN + 2 * NB) * (int)sizeof(int);   // 98,304 bytes
    cudaFuncSetAttribute(fused, cudaFuncAttributeMaxDynamicSharedMemorySize, smem);
    fused<<<GRID, TPB, smem>>>(ei, p, x, (float*)d_out, E, n, logn);
}